// round 3
// baseline (speedup 1.0000x reference)
#include <cuda_runtime.h>
#include <cstdint>

#define MROWS  4096   // B*T
#define DMODEL 1024
#define T_SEQ  2048
#define NB     2
#define NH     16
#define DH     64

// ---------------- scratch (__device__ globals: allocation-free rule) --------
__device__ float g_Q[MROWS * DMODEL];
__device__ float g_K[MROWS * DMODEL];
__device__ float g_V[MROWS * DMODEL];
__device__ float g_Z[MROWS * DMODEL];

__device__ uint32_t g_xh[MROWS * DMODEL],  g_xl[MROWS * DMODEL];
__device__ uint32_t g_Zh[MROWS * DMODEL],  g_Zl[MROWS * DMODEL];
__device__ uint32_t g_Wqh[DMODEL * DMODEL], g_Wql[DMODEL * DMODEL];
__device__ uint32_t g_Wkh[DMODEL * DMODEL], g_Wkl[DMODEL * DMODEL];
__device__ uint32_t g_Wvh[DMODEL * DMODEL], g_Wvl[DMODEL * DMODEL];
__device__ uint32_t g_Woh[DMODEL * DMODEL], g_Wol[DMODEL * DMODEL];

// ---------------------------------------------------------------------------
__device__ __forceinline__ uint32_t tf32_of(float v) {
    uint32_t r;
    asm("cvt.rna.tf32.f32 %0, %1;" : "=r"(r) : "f"(v));
    return r;
}

__device__ __forceinline__ void mma_tf32(float* c, const uint32_t* a,
                                         uint32_t b0, uint32_t b1) {
    asm volatile(
        "mma.sync.aligned.m16n8k8.row.col.f32.tf32.tf32.f32 "
        "{%0,%1,%2,%3}, {%4,%5,%6,%7}, {%8,%9}, {%0,%1,%2,%3};"
        : "+f"(c[0]), "+f"(c[1]), "+f"(c[2]), "+f"(c[3])
        : "r"(a[0]), "r"(a[1]), "r"(a[2]), "r"(a[3]), "r"(b0), "r"(b1));
}

// ---------------------------------------------------------------------------
// Split fp32 -> (tf32 hi, tf32 lo). n4 = element count / 4.
// ---------------------------------------------------------------------------
__global__ __launch_bounds__(256) void split_k(const float* __restrict__ src,
                                               uint32_t* __restrict__ hi,
                                               uint32_t* __restrict__ lo, int n4)
{
    int i = blockIdx.x * 256 + threadIdx.x;
    if (i >= n4) return;
    float4 v = ((const float4*)src)[i];
    uint4 h, l;
    h.x = tf32_of(v.x); l.x = tf32_of(v.x - __uint_as_float(h.x));
    h.y = tf32_of(v.y); l.y = tf32_of(v.y - __uint_as_float(h.y));
    h.z = tf32_of(v.z); l.z = tf32_of(v.z - __uint_as_float(h.z));
    h.w = tf32_of(v.w); l.w = tf32_of(v.w - __uint_as_float(h.w));
    ((uint4*)hi)[i] = h;
    ((uint4*)lo)[i] = l;
}

// ---------------------------------------------------------------------------
// Tensor-core GEMM (tf32, 3x split): C[M,N] = A[M,K]*W[K,N], M=4096, N=K=1024.
// 128x128 block tile, BK=16, 256 threads, 8 warps as 2x4 (warp tile m64 x n32).
// Register prefetch of next K-tile overlaps global latency with MMA compute.
// ---------------------------------------------------------------------------
__global__ __launch_bounds__(256) void gemm_tc(const uint32_t* __restrict__ Ah,
                                               const uint32_t* __restrict__ Al,
                                               const uint32_t* __restrict__ Wh,
                                               const uint32_t* __restrict__ Wl,
                                               float* __restrict__ C)
{
    __shared__ uint32_t AsH[128][20], AsL[128][20];   // [m][k], pad->stride 20
    __shared__ uint32_t WsH[16][136], WsL[16][136];   // [k][n], pad->stride 136

    const int tid  = threadIdx.x;
    const int lane = tid & 31;
    const int gid  = lane >> 2;     // 0..7
    const int ctg  = lane & 3;      // 0..3
    const int wid  = tid >> 5;
    const int wm   = wid & 1;       // 0..1  (m64 slabs)
    const int wn   = wid >> 1;      // 0..3  (n32 slabs)
    const int row0 = blockIdx.y * 128;
    const int col0 = blockIdx.x * 128;

    // loader indices (two chunks c=0,1; 512 float4 per tile buffer)
    const int am = tid >> 2;              // + 64*c
    const int ak = (tid & 3) << 2;
    const int wk = tid >> 5;              // + 8*c
    const int wn4 = (tid & 31) << 2;

    float acc[4][4][4];
#pragma unroll
    for (int a = 0; a < 4; a++)
#pragma unroll
        for (int b = 0; b < 4; b++)
#pragma unroll
            for (int d = 0; d < 4; d++) acc[a][b][d] = 0.f;

    uint4 pAh[2], pAl[2], pWh[2], pWl[2];

    // prefetch tile 0
#pragma unroll
    for (int c = 0; c < 2; c++) {
        size_t ga = (size_t)(row0 + am + 64 * c) * DMODEL + ak;
        pAh[c] = *(const uint4*)&Ah[ga];
        pAl[c] = *(const uint4*)&Al[ga];
        size_t gw = (size_t)(wk + 8 * c) * DMODEL + col0 + wn4;
        pWh[c] = *(const uint4*)&Wh[gw];
        pWl[c] = *(const uint4*)&Wl[gw];
    }

    for (int kt = 0; kt < DMODEL / 16; kt++) {
        // commit prefetched tile to smem
#pragma unroll
        for (int c = 0; c < 2; c++) {
            *(uint4*)&AsH[am + 64 * c][ak]  = pAh[c];
            *(uint4*)&AsL[am + 64 * c][ak]  = pAl[c];
            *(uint4*)&WsH[wk + 8 * c][wn4]  = pWh[c];
            *(uint4*)&WsL[wk + 8 * c][wn4]  = pWl[c];
        }
        __syncthreads();

        // issue next tile's loads (latency hidden under MMA below)
        if (kt + 1 < DMODEL / 16) {
            const int k0 = (kt + 1) * 16;
#pragma unroll
            for (int c = 0; c < 2; c++) {
                size_t ga = (size_t)(row0 + am + 64 * c) * DMODEL + k0 + ak;
                pAh[c] = *(const uint4*)&Ah[ga];
                pAl[c] = *(const uint4*)&Al[ga];
                size_t gw = (size_t)(k0 + wk + 8 * c) * DMODEL + col0 + wn4;
                pWh[c] = *(const uint4*)&Wh[gw];
                pWl[c] = *(const uint4*)&Wl[gw];
            }
        }

#pragma unroll
        for (int ks = 0; ks < 16; ks += 8) {
            uint32_t ah[4][4], al[4][4];
#pragma unroll
            for (int mi = 0; mi < 4; mi++) {
                int m0 = wm * 64 + mi * 16;
                ah[mi][0] = AsH[m0 + gid    ][ks + ctg];
                ah[mi][1] = AsH[m0 + gid + 8][ks + ctg];
                ah[mi][2] = AsH[m0 + gid    ][ks + ctg + 4];
                ah[mi][3] = AsH[m0 + gid + 8][ks + ctg + 4];
                al[mi][0] = AsL[m0 + gid    ][ks + ctg];
                al[mi][1] = AsL[m0 + gid + 8][ks + ctg];
                al[mi][2] = AsL[m0 + gid    ][ks + ctg + 4];
                al[mi][3] = AsL[m0 + gid + 8][ks + ctg + 4];
            }
#pragma unroll
            for (int ni = 0; ni < 4; ni++) {
                int n = wn * 32 + ni * 8 + gid;
                uint32_t bh0 = WsH[ks + ctg][n];
                uint32_t bh1 = WsH[ks + ctg + 4][n];
                uint32_t bl0 = WsL[ks + ctg][n];
                uint32_t bl1 = WsL[ks + ctg + 4][n];
#pragma unroll
                for (int mi = 0; mi < 4; mi++) {
                    mma_tf32(acc[mi][ni], ah[mi], bh0, bh1);  // hi*hi
                    mma_tf32(acc[mi][ni], ah[mi], bl0, bl1);  // hi*lo
                    mma_tf32(acc[mi][ni], al[mi], bh0, bh1);  // lo*hi
                }
            }
        }
        __syncthreads();
    }

    // epilogue
#pragma unroll
    for (int mi = 0; mi < 4; mi++) {
        int r0 = row0 + wm * 64 + mi * 16 + gid;
#pragma unroll
        for (int ni = 0; ni < 4; ni++) {
            int cc = col0 + wn * 32 + ni * 8 + ctg * 2;
            *(float2*)&C[(size_t)r0 * DMODEL + cc] =
                make_float2(acc[mi][ni][0], acc[mi][ni][1]);
            *(float2*)&C[(size_t)(r0 + 8) * DMODEL + cc] =
                make_float2(acc[mi][ni][2], acc[mi][ni][3]);
        }
    }
}

// ---------------------------------------------------------------------------
// Causal flash attention, fp32 (unchanged from R0 — tensorize next round).
// ---------------------------------------------------------------------------
__global__ __launch_bounds__(128) void attn_k()
{
    __shared__ float Ks[64][64];
    __shared__ float Vs[64][64];

    const int tid  = threadIdx.x;
    const int bh   = blockIdx.y;
    const int b    = bh >> 4;
    const int h    = bh & 15;
    const int base = b * T_SEQ;
    const int i    = blockIdx.x * 128 + tid;
    const int h64  = h * DH;
    const float scale = 0.125f;

    float q[DH], o[DH];
    const float* qrow = &g_Q[(size_t)(base + i) * DMODEL + h64];
#pragma unroll
    for (int k = 0; k < DH; k += 4) {
        float4 v = *(const float4*)&qrow[k];
        q[k] = v.x; q[k + 1] = v.y; q[k + 2] = v.z; q[k + 3] = v.w;
    }
#pragma unroll
    for (int k = 0; k < DH; k++) o[k] = 0.f;
    float m = -1e30f, l = 0.f;

    const int ntiles = (blockIdx.x * 128 + 128) / 64;
    for (int t = 0; t < ntiles; t++) {
        const int kt = t * 64;
        const float* Kg = &g_K[(size_t)(base + kt) * DMODEL + h64];
        const float* Vg = &g_V[(size_t)(base + kt) * DMODEL + h64];
#pragma unroll
        for (int c = 0; c < 8; c++) {
            int f  = tid + 128 * c;
            int j  = f >> 4;
            int k4 = (f & 15) << 2;
            *(float4*)&Ks[j][k4] = *(const float4*)&Kg[(size_t)j * DMODEL + k4];
            *(float4*)&Vs[j][k4] = *(const float4*)&Vg[(size_t)j * DMODEL + k4];
        }
        __syncthreads();

        if (i >= kt) {
#pragma unroll 1
            for (int j0 = 0; j0 < 64; j0 += 8) {
                if (kt + j0 > i) break;
                float s[8];
#pragma unroll
                for (int jj = 0; jj < 8; jj++) {
                    const float* kr = Ks[j0 + jj];
                    float a0 = 0.f, a1 = 0.f, a2 = 0.f, a3 = 0.f;
#pragma unroll
                    for (int k = 0; k < DH; k += 4) {
                        a0 += q[k]     * kr[k];
                        a1 += q[k + 1] * kr[k + 1];
                        a2 += q[k + 2] * kr[k + 2];
                        a3 += q[k + 3] * kr[k + 3];
                    }
                    float sv = (a0 + a1) + (a2 + a3);
                    s[jj] = sv * scale + ((kt + j0 + jj <= i) ? 0.f : -1e30f);
                }
                float cm = s[0];
#pragma unroll
                for (int jj = 1; jj < 8; jj++) cm = fmaxf(cm, s[jj]);
                if (cm > m) {
                    float corr = __expf(m - cm);
                    m = cm;
                    l *= corr;
#pragma unroll
                    for (int k = 0; k < DH; k++) o[k] *= corr;
                }
#pragma unroll
                for (int jj = 0; jj < 8; jj++) {
                    float p = __expf(s[jj] - m);
                    l += p;
                    const float* vr = Vs[j0 + jj];
#pragma unroll
                    for (int k = 0; k < DH; k++) o[k] += p * vr[k];
                }
            }
        }
        __syncthreads();
    }

    const float inv = 1.f / l;
    float* zrow = &g_Z[(size_t)(base + i) * DMODEL + h64];
#pragma unroll
    for (int k = 0; k < DH; k += 4) {
        *(float4*)&zrow[k] = make_float4(o[k] * inv, o[k + 1] * inv,
                                         o[k + 2] * inv, o[k + 3] * inv);
    }
}

// ---------------------------------------------------------------------------
extern "C" void kernel_launch(void* const* d_in, const int* in_sizes, int n_in,
                              void* d_out, int out_size)
{
    const float* x  = (const float*)d_in[0];
    const float* Wq = (const float*)d_in[1];
    const float* Wk = (const float*)d_in[2];
    const float* Wv = (const float*)d_in[3];
    const float* Wo = (const float*)d_in[4];
    float* out = (float*)d_out;

    float *Q, *K, *V, *Z;
    cudaGetSymbolAddress((void**)&Q, g_Q);
    cudaGetSymbolAddress((void**)&K, g_K);
    cudaGetSymbolAddress((void**)&V, g_V);
    cudaGetSymbolAddress((void**)&Z, g_Z);

    uint32_t *xh, *xl, *Zh, *Zl;
    uint32_t *Wqh, *Wql, *Wkh, *Wkl, *Wvh, *Wvl, *Woh, *Wol;
    cudaGetSymbolAddress((void**)&xh, g_xh);   cudaGetSymbolAddress((void**)&xl, g_xl);
    cudaGetSymbolAddress((void**)&Zh, g_Zh);   cudaGetSymbolAddress((void**)&Zl, g_Zl);
    cudaGetSymbolAddress((void**)&Wqh, g_Wqh); cudaGetSymbolAddress((void**)&Wql, g_Wql);
    cudaGetSymbolAddress((void**)&Wkh, g_Wkh); cudaGetSymbolAddress((void**)&Wkl, g_Wkl);
    cudaGetSymbolAddress((void**)&Wvh, g_Wvh); cudaGetSymbolAddress((void**)&Wvl, g_Wvl);
    cudaGetSymbolAddress((void**)&Woh, g_Woh); cudaGetSymbolAddress((void**)&Wol, g_Wol);

    const int nx4 = MROWS * DMODEL / 4;     // x / Z float4 count
    const int nw4 = DMODEL * DMODEL / 4;    // W float4 count

    split_k<<<(nx4 + 255) / 256, 256>>>(x,  xh,  xl,  nx4);
    split_k<<<(nw4 + 255) / 256, 256>>>(Wq, Wqh, Wql, nw4);
    split_k<<<(nw4 + 255) / 256, 256>>>(Wk, Wkh, Wkl, nw4);
    split_k<<<(nw4 + 255) / 256, 256>>>(Wv, Wvh, Wvl, nw4);
    split_k<<<(nw4 + 255) / 256, 256>>>(Wo, Woh, Wol, nw4);

    dim3 ggrid(DMODEL / 128, MROWS / 128);  // (8, 32)
    gemm_tc<<<ggrid, 256>>>(xh, xl, Wqh, Wql, Q);
    gemm_tc<<<ggrid, 256>>>(xh, xl, Wkh, Wkl, K);
    gemm_tc<<<ggrid, 256>>>(xh, xl, Wvh, Wvl, V);

    attn_k<<<dim3(T_SEQ / 128, NB * NH), 128>>>();

    split_k<<<(nx4 + 255) / 256, 256>>>(Z, Zh, Zl, nx4);
    gemm_tc<<<ggrid, 256>>>(Zh, Zl, Woh, Wol, out);
}

// round 5
// speedup vs baseline: 2.1122x; 2.1122x over previous
#include <cuda_runtime.h>
#include <cuda_bf16.h>
#include <cstdint>

#define MROWS  4096   // B*T
#define DMODEL 1024
#define T_SEQ  2048
#define NB     2
#define NH     16
#define DH     64

// ---------------- scratch (__device__ globals: allocation-free rule) --------
__device__ float g_Q[MROWS * DMODEL];
__device__ float g_K[MROWS * DMODEL];
__device__ float g_V[MROWS * DMODEL];
__device__ float g_Z[MROWS * DMODEL];

// bf16 split operands
__device__ __nv_bfloat16 g_xh[MROWS * DMODEL],  g_xl[MROWS * DMODEL];
__device__ __nv_bfloat16 g_Zh[MROWS * DMODEL],  g_Zl[MROWS * DMODEL];
// weights, transposed to [N,K]
__device__ __nv_bfloat16 g_Wqh[DMODEL * DMODEL], g_Wql[DMODEL * DMODEL];
__device__ __nv_bfloat16 g_Wkh[DMODEL * DMODEL], g_Wkl[DMODEL * DMODEL];
__device__ __nv_bfloat16 g_Wvh[DMODEL * DMODEL], g_Wvl[DMODEL * DMODEL];
__device__ __nv_bfloat16 g_Woh[DMODEL * DMODEL], g_Wol[DMODEL * DMODEL];

// ---------------------------------------------------------------------------
// PTX helpers (plain sm_103 features only: cp.async, ldmatrix, mma.sync)
// ---------------------------------------------------------------------------
__device__ __forceinline__ uint32_t smem_u32(const void* p) {
    uint32_t a;
    asm("{ .reg .u64 t; cvta.to.shared.u64 t, %1; cvt.u32.u64 %0, t; }"
        : "=r"(a) : "l"(p));
    return a;
}

__device__ __forceinline__ void cp_async16(uint32_t dst, const void* src) {
    asm volatile("cp.async.cg.shared.global [%0], [%1], 16;"
                 :: "r"(dst), "l"(src));
}
#define CP_COMMIT() asm volatile("cp.async.commit_group;" ::: "memory")
#define CP_WAIT(n)  asm volatile("cp.async.wait_group %0;" :: "n"(n) : "memory")

__device__ __forceinline__ void ldsm_x4(uint32_t* r, uint32_t addr) {
    asm volatile("ldmatrix.sync.aligned.m8n8.x4.shared.b16 {%0,%1,%2,%3}, [%4];"
                 : "=r"(r[0]), "=r"(r[1]), "=r"(r[2]), "=r"(r[3]) : "r"(addr));
}

__device__ __forceinline__ void mma_bf16(float* c, const uint32_t* a,
                                         uint32_t b0, uint32_t b1) {
    asm volatile(
        "mma.sync.aligned.m16n8k16.row.col.f32.bf16.bf16.f32 "
        "{%0,%1,%2,%3}, {%4,%5,%6,%7}, {%8,%9}, {%0,%1,%2,%3};"
        : "+f"(c[0]), "+f"(c[1]), "+f"(c[2]), "+f"(c[3])
        : "r"(a[0]), "r"(a[1]), "r"(a[2]), "r"(a[3]), "r"(b0), "r"(b1));
}

// ---------------------------------------------------------------------------
// Split kernels
// ---------------------------------------------------------------------------
__global__ __launch_bounds__(256) void split_x(const float* __restrict__ src,
                                               __nv_bfloat16* __restrict__ hi,
                                               __nv_bfloat16* __restrict__ lo, int n4)
{
    int i = blockIdx.x * 256 + threadIdx.x;
    if (i >= n4) return;
    float4 v = ((const float4*)src)[i];
    __nv_bfloat16 h[4], l[4];
    float vv[4] = {v.x, v.y, v.z, v.w};
#pragma unroll
    for (int k = 0; k < 4; k++) {
        h[k] = __float2bfloat16_rn(vv[k]);
        l[k] = __float2bfloat16_rn(vv[k] - __bfloat162float(h[k]));
    }
    ((uint2*)hi)[i] = *(uint2*)h;
    ((uint2*)lo)[i] = *(uint2*)l;
}

// W[K,N] fp32 -> transposed bf16 hi/lo [N,K]
__global__ __launch_bounds__(256) void split_wt(const float* __restrict__ W,
                                                __nv_bfloat16* __restrict__ Th,
                                                __nv_bfloat16* __restrict__ Tl)
{
    __shared__ float tile[32][33];
    const int tx = threadIdx.x, ty = threadIdx.y;        // (32, 8)
    const int bn = blockIdx.x * 32, bk = blockIdx.y * 32;
#pragma unroll
    for (int j = 0; j < 32; j += 8)
        tile[ty + j][tx] = W[(size_t)(bk + ty + j) * DMODEL + bn + tx];
    __syncthreads();
#pragma unroll
    for (int j = 0; j < 32; j += 8) {
        float v = tile[tx][ty + j];
        __nv_bfloat16 h = __float2bfloat16_rn(v);
        __nv_bfloat16 l = __float2bfloat16_rn(v - __bfloat162float(h));
        Th[(size_t)(bn + ty + j) * DMODEL + bk + tx] = h;
        Tl[(size_t)(bn + ty + j) * DMODEL + bk + tx] = l;
    }
}

// ---------------------------------------------------------------------------
// bf16 mma.sync GEMM, 3-term split: C[M,N] = A[M,K] * B[N,K]^T, fp32 out.
// CTA 128x128, BK=32, 8 warps (4m x 2n -> warp tile 32x64), cp.async x2 stage.
// Both operands [row][k] K-contiguous in smem, 80B row stride (conflict-free
// ldmatrix: banks m*20 mod 32 distinct over 8 rows).
// ---------------------------------------------------------------------------
#define BK        32
#define RSTRIDE   40                        // bf16 elems per smem row (32+8 pad)
#define TILE_B    (128 * RSTRIDE * 2)       // 10240 B per 128x32 tile
#define STAGE_B   (4 * TILE_B)              // Ah,Al,Bh,Bl
#define NSTAGE    (DMODEL / BK)             // 32

extern __shared__ char dyn_smem[];

__global__ __launch_bounds__(256, 2) void gemm_bf16(
    const __nv_bfloat16* __restrict__ Ah, const __nv_bfloat16* __restrict__ Al,
    const __nv_bfloat16* __restrict__ Bh, const __nv_bfloat16* __restrict__ Bl,
    float* __restrict__ C)
{
    const uint32_t sb = smem_u32(dyn_smem);
    const int tid  = threadIdx.x;
    const int lane = tid & 31;
    const int wid  = tid >> 5;
    const int m0   = (wid & 3) * 32;        // warp m-slab within CTA tile
    const int n0   = (wid >> 2) * 64;       // warp n-slab
    const int row0 = blockIdx.y * 128;
    const int col0 = blockIdx.x * 128;

    const __nv_bfloat16* srcs[4] = {Ah, Al, Bh, Bl};

    float acc[2][8][4];
#pragma unroll
    for (int a = 0; a < 2; a++)
#pragma unroll
        for (int b = 0; b < 8; b++)
#pragma unroll
            for (int d = 0; d < 4; d++) acc[a][b][d] = 0.f;

    // per-lane ldmatrix address components
    const int a_row = lane & 15;             // + m0 + mi*16
    const int a_col = 8 * (lane >> 4);       // + kk
    const int b_row = (lane & 7) + 8 * (lane >> 4);   // + n0 + ng*16
    const int b_col = 8 * ((lane >> 3) & 1);          // + kk

    auto load_stage = [&](int s) {
        const uint32_t base = sb + (uint32_t)(s & 1) * STAGE_B;
        const int k0 = s * BK;
#pragma unroll
        for (int t = 0; t < 4; t++) {
            const uint32_t tb = base + (uint32_t)t * TILE_B;
            const int gr0 = (t < 2) ? row0 : col0;
#pragma unroll
            for (int i = 0; i < 2; i++) {
                int f  = tid + i * 256;       // 0..511
                int r  = f >> 2;              // 0..127
                int ch = f & 3;               // 16B chunk (8 bf16)
                cp_async16(tb + (uint32_t)(r * 80 + ch * 16),
                           srcs[t] + (size_t)(gr0 + r) * DMODEL + k0 + ch * 8);
            }
        }
        CP_COMMIT();
    };

    load_stage(0);

    for (int s = 0; s < NSTAGE; s++) {
        if (s + 1 < NSTAGE) { load_stage(s + 1); CP_WAIT(1); }
        else                 { CP_WAIT(0); }
        __syncthreads();

        const uint32_t base = sb + (uint32_t)(s & 1) * STAGE_B;
        const uint32_t aHB = base, aLB = base + TILE_B;
        const uint32_t bHB = base + 2 * TILE_B, bLB = base + 3 * TILE_B;

#pragma unroll
        for (int kk = 0; kk < BK; kk += 16) {
            uint32_t ah[2][4], al[2][4];
#pragma unroll
            for (int mi = 0; mi < 2; mi++) {
                uint32_t off = (uint32_t)((m0 + mi * 16 + a_row) * 80 +
                                          (kk + a_col) * 2);
                ldsm_x4(ah[mi], aHB + off);
                ldsm_x4(al[mi], aLB + off);
            }
#pragma unroll
            for (int ng = 0; ng < 4; ng++) {
                uint32_t boff = (uint32_t)((n0 + ng * 16 + b_row) * 80 +
                                           (kk + b_col) * 2);
                uint32_t bh[4], bl[4];
                ldsm_x4(bh, bHB + boff);
                ldsm_x4(bl, bLB + boff);
#pragma unroll
                for (int mi = 0; mi < 2; mi++) {
                    mma_bf16(acc[mi][2 * ng],     ah[mi], bh[0], bh[1]);
                    mma_bf16(acc[mi][2 * ng + 1], ah[mi], bh[2], bh[3]);
                    mma_bf16(acc[mi][2 * ng],     ah[mi], bl[0], bl[1]);
                    mma_bf16(acc[mi][2 * ng + 1], ah[mi], bl[2], bl[3]);
                    mma_bf16(acc[mi][2 * ng],     al[mi], bh[0], bh[1]);
                    mma_bf16(acc[mi][2 * ng + 1], al[mi], bh[2], bh[3]);
                }
            }
        }
        __syncthreads();
    }

    // epilogue: c-frag (c0,c1)@(lane/4, (lane%4)*2), (c2,c3)@(+8 row)
#pragma unroll
    for (int mi = 0; mi < 2; mi++) {
        int r = row0 + m0 + mi * 16 + (lane >> 2);
#pragma unroll
        for (int nj = 0; nj < 8; nj++) {
            int c = col0 + n0 + nj * 8 + (lane & 3) * 2;
            *(float2*)&C[(size_t)r * DMODEL + c] =
                make_float2(acc[mi][nj][0], acc[mi][nj][1]);
            *(float2*)&C[(size_t)(r + 8) * DMODEL + c] =
                make_float2(acc[mi][nj][2], acc[mi][nj][3]);
        }
    }
}

// ---------------------------------------------------------------------------
// Causal flash attention, fp32 (unchanged — next round's target).
// ---------------------------------------------------------------------------
__global__ __launch_bounds__(128) void attn_k()
{
    __shared__ float Ks[64][64];
    __shared__ float Vs[64][64];

    const int tid  = threadIdx.x;
    const int bh   = blockIdx.y;
    const int b    = bh >> 4;
    const int h    = bh & 15;
    const int base = b * T_SEQ;
    const int i    = blockIdx.x * 128 + tid;
    const int h64  = h * DH;
    const float scale = 0.125f;

    float q[DH], o[DH];
    const float* qrow = &g_Q[(size_t)(base + i) * DMODEL + h64];
#pragma unroll
    for (int k = 0; k < DH; k += 4) {
        float4 v = *(const float4*)&qrow[k];
        q[k] = v.x; q[k + 1] = v.y; q[k + 2] = v.z; q[k + 3] = v.w;
    }
#pragma unroll
    for (int k = 0; k < DH; k++) o[k] = 0.f;
    float m = -1e30f, l = 0.f;

    const int ntiles = (blockIdx.x * 128 + 128) / 64;
    for (int t = 0; t < ntiles; t++) {
        const int kt = t * 64;
        const float* Kg = &g_K[(size_t)(base + kt) * DMODEL + h64];
        const float* Vg = &g_V[(size_t)(base + kt) * DMODEL + h64];
#pragma unroll
        for (int c = 0; c < 8; c++) {
            int f  = tid + 128 * c;
            int j  = f >> 4;
            int k4 = (f & 15) << 2;
            *(float4*)&Ks[j][k4] = *(const float4*)&Kg[(size_t)j * DMODEL + k4];
            *(float4*)&Vs[j][k4] = *(const float4*)&Vg[(size_t)j * DMODEL + k4];
        }
        __syncthreads();

        if (i >= kt) {
#pragma unroll 1
            for (int j0 = 0; j0 < 64; j0 += 8) {
                if (kt + j0 > i) break;
                float s[8];
#pragma unroll
                for (int jj = 0; jj < 8; jj++) {
                    const float* kr = Ks[j0 + jj];
                    float a0 = 0.f, a1 = 0.f, a2 = 0.f, a3 = 0.f;
#pragma unroll
                    for (int k = 0; k < DH; k += 4) {
                        a0 += q[k]     * kr[k];
                        a1 += q[k + 1] * kr[k + 1];
                        a2 += q[k + 2] * kr[k + 2];
                        a3 += q[k + 3] * kr[k + 3];
                    }
                    float sv = (a0 + a1) + (a2 + a3);
                    s[jj] = sv * scale + ((kt + j0 + jj <= i) ? 0.f : -1e30f);
                }
                float cm = s[0];
#pragma unroll
                for (int jj = 1; jj < 8; jj++) cm = fmaxf(cm, s[jj]);
                if (cm > m) {
                    float corr = __expf(m - cm);
                    m = cm;
                    l *= corr;
#pragma unroll
                    for (int k = 0; k < DH; k++) o[k] *= corr;
                }
#pragma unroll
                for (int jj = 0; jj < 8; jj++) {
                    float p = __expf(s[jj] - m);
                    l += p;
                    const float* vr = Vs[j0 + jj];
#pragma unroll
                    for (int k = 0; k < DH; k++) o[k] += p * vr[k];
                }
            }
        }
        __syncthreads();
    }

    const float inv = 1.f / l;
    float* zrow = &g_Z[(size_t)(base + i) * DMODEL + h64];
#pragma unroll
    for (int k = 0; k < DH; k += 4) {
        *(float4*)&zrow[k] = make_float4(o[k] * inv, o[k + 1] * inv,
                                         o[k + 2] * inv, o[k + 3] * inv);
    }
}

// ---------------------------------------------------------------------------
extern "C" void kernel_launch(void* const* d_in, const int* in_sizes, int n_in,
                              void* d_out, int out_size)
{
    const float* x  = (const float*)d_in[0];
    const float* Wq = (const float*)d_in[1];
    const float* Wk = (const float*)d_in[2];
    const float* Wv = (const float*)d_in[3];
    const float* Wo = (const float*)d_in[4];
    float* out = (float*)d_out;

    float *Q, *K, *V, *Z;
    cudaGetSymbolAddress((void**)&Q, g_Q);
    cudaGetSymbolAddress((void**)&K, g_K);
    cudaGetSymbolAddress((void**)&V, g_V);
    cudaGetSymbolAddress((void**)&Z, g_Z);

    __nv_bfloat16 *xh, *xl, *Zh, *Zl;
    __nv_bfloat16 *Wqh, *Wql, *Wkh, *Wkl, *Wvh, *Wvl, *Woh, *Wol;
    cudaGetSymbolAddress((void**)&xh, g_xh);   cudaGetSymbolAddress((void**)&xl, g_xl);
    cudaGetSymbolAddress((void**)&Zh, g_Zh);   cudaGetSymbolAddress((void**)&Zl, g_Zl);
    cudaGetSymbolAddress((void**)&Wqh, g_Wqh); cudaGetSymbolAddress((void**)&Wql, g_Wql);
    cudaGetSymbolAddress((void**)&Wkh, g_Wkh); cudaGetSymbolAddress((void**)&Wkl, g_Wkl);
    cudaGetSymbolAddress((void**)&Wvh, g_Wvh); cudaGetSymbolAddress((void**)&Wvl, g_Wvl);
    cudaGetSymbolAddress((void**)&Woh, g_Woh); cudaGetSymbolAddress((void**)&Wol, g_Wol);

    // dynamic smem: 2 stages x (Ah,Al,Bh,Bl) = 81920 B (set attr every call;
    // deterministic, not a stream op -> capture-safe)
    cudaFuncSetAttribute(gemm_bf16, cudaFuncAttributeMaxDynamicSharedMemorySize,
                         2 * STAGE_B);

    const int nx4 = MROWS * DMODEL / 4;
    dim3 tblk(32, 8), tgrd(DMODEL / 32, DMODEL / 32);

    split_x<<<(nx4 + 255) / 256, 256>>>(x, xh, xl, nx4);
    split_wt<<<tgrd, tblk>>>(Wq, Wqh, Wql);
    split_wt<<<tgrd, tblk>>>(Wk, Wkh, Wkl);
    split_wt<<<tgrd, tblk>>>(Wv, Wvh, Wvl);
    split_wt<<<tgrd, tblk>>>(Wo, Woh, Wol);

    dim3 ggrid(DMODEL / 128, MROWS / 128);   // (8, 32)
    gemm_bf16<<<ggrid, 256, 2 * STAGE_B>>>(xh, xl, Wqh, Wql, Q);
    gemm_bf16<<<ggrid, 256, 2 * STAGE_B>>>(xh, xl, Wkh, Wkl, K);
    gemm_bf16<<<ggrid, 256, 2 * STAGE_B>>>(xh, xl, Wvh, Wvl, V);

    attn_k<<<dim3(T_SEQ / 128, NB * NH), 128>>>();

    split_x<<<(nx4 + 255) / 256, 256>>>(Z, Zh, Zl, nx4);
    gemm_bf16<<<ggrid, 256, 2 * STAGE_B>>>(Zh, Zl, Woh, Wol, out);
}

// round 8
// speedup vs baseline: 2.8313x; 1.3405x over previous
#include <cuda_runtime.h>
#include <cuda_bf16.h>
#include <cstdint>

#define MROWS  4096   // B*T
#define DMODEL 1024
#define T_SEQ  2048
#define NB     2
#define NH     16
#define DH     64
#define QSCALE 0.1803368801111244f   // 0.125 * log2(e)

// ---------------- scratch (__device__ globals: allocation-free rule) --------
__device__ __nv_bfloat16 g_xh[MROWS * DMODEL],  g_xl[MROWS * DMODEL];
__device__ __nv_bfloat16 g_Qh[MROWS * DMODEL],  g_Ql[MROWS * DMODEL];
__device__ __nv_bfloat16 g_Kh[MROWS * DMODEL],  g_Kl[MROWS * DMODEL];
__device__ __nv_bfloat16 g_Vh[MROWS * DMODEL],  g_Vl[MROWS * DMODEL];
__device__ __nv_bfloat16 g_Zh[MROWS * DMODEL],  g_Zl[MROWS * DMODEL];
__device__ __nv_bfloat16 g_Wqh[DMODEL * DMODEL], g_Wql[DMODEL * DMODEL];
__device__ __nv_bfloat16 g_Wkh[DMODEL * DMODEL], g_Wkl[DMODEL * DMODEL];
__device__ __nv_bfloat16 g_Wvh[DMODEL * DMODEL], g_Wvl[DMODEL * DMODEL];
__device__ __nv_bfloat16 g_Woh[DMODEL * DMODEL], g_Wol[DMODEL * DMODEL];

// ---------------------------------------------------------------------------
// PTX helpers (plain sm_103: cp.async, ldmatrix, mma.sync, ex2.approx)
// ---------------------------------------------------------------------------
__device__ __forceinline__ uint32_t smem_u32(const void* p) {
    uint32_t a;
    asm("{ .reg .u64 t; cvta.to.shared.u64 t, %1; cvt.u32.u64 %0, t; }"
        : "=r"(a) : "l"(p));
    return a;
}

__device__ __forceinline__ void cp_async16(uint32_t dst, const void* src) {
    asm volatile("cp.async.cg.shared.global [%0], [%1], 16;"
                 :: "r"(dst), "l"(src));
}
#define CP_COMMIT() asm volatile("cp.async.commit_group;" ::: "memory")
#define CP_WAIT(n)  asm volatile("cp.async.wait_group %0;" :: "n"(n) : "memory")

// 128B-row XOR swizzle (chunk ^= row&7) — same formula at store and load
#define SW128(off) ((off) ^ (((off) >> 3) & 0x70))

__device__ __forceinline__ void ldsm_x4(uint32_t* r, uint32_t addr) {
    asm volatile("ldmatrix.sync.aligned.m8n8.x4.shared.b16 {%0,%1,%2,%3}, [%4];"
                 : "=r"(r[0]), "=r"(r[1]), "=r"(r[2]), "=r"(r[3]) : "r"(addr));
}
__device__ __forceinline__ void ldsm_x4_t(uint32_t* r, uint32_t addr) {
    asm volatile("ldmatrix.sync.aligned.m8n8.x4.trans.shared.b16 {%0,%1,%2,%3}, [%4];"
                 : "=r"(r[0]), "=r"(r[1]), "=r"(r[2]), "=r"(r[3]) : "r"(addr));
}

__device__ __forceinline__ void mma_bf16(float* c, const uint32_t* a,
                                         uint32_t b0, uint32_t b1) {
    asm volatile(
        "mma.sync.aligned.m16n8k16.row.col.f32.bf16.bf16.f32 "
        "{%0,%1,%2,%3}, {%4,%5,%6,%7}, {%8,%9}, {%0,%1,%2,%3};"
        : "+f"(c[0]), "+f"(c[1]), "+f"(c[2]), "+f"(c[3])
        : "r"(a[0]), "r"(a[1]), "r"(a[2]), "r"(a[3]), "r"(b0), "r"(b1));
}

__device__ __forceinline__ float ex2(float x) {
    float r;
    asm("ex2.approx.f32 %0, %1;" : "=f"(r) : "f"(x));
    return r;
}

__device__ __forceinline__ uint32_t split2(float v0, float v1, uint32_t& lo) {
    __nv_bfloat16 h0 = __float2bfloat16_rn(v0), h1 = __float2bfloat16_rn(v1);
    float l0 = v0 - __bfloat162float(h0), l1 = v1 - __bfloat162float(h1);
    __nv_bfloat16 L0 = __float2bfloat16_rn(l0), L1 = __float2bfloat16_rn(l1);
    lo = (uint32_t)__bfloat16_as_ushort(L0) | ((uint32_t)__bfloat16_as_ushort(L1) << 16);
    return (uint32_t)__bfloat16_as_ushort(h0) | ((uint32_t)__bfloat16_as_ushort(h1) << 16);
}

// ---------------------------------------------------------------------------
// Split kernels (inputs only)
// ---------------------------------------------------------------------------
__global__ __launch_bounds__(256) void split_x(const float* __restrict__ src,
                                               __nv_bfloat16* __restrict__ hi,
                                               __nv_bfloat16* __restrict__ lo, int n4)
{
    int i = blockIdx.x * 256 + threadIdx.x;
    if (i >= n4) return;
    float4 v = ((const float4*)src)[i];
    __nv_bfloat16 h[4], l[4];
    float vv[4] = {v.x, v.y, v.z, v.w};
#pragma unroll
    for (int k = 0; k < 4; k++) {
        h[k] = __float2bfloat16_rn(vv[k]);
        l[k] = __float2bfloat16_rn(vv[k] - __bfloat162float(h[k]));
    }
    ((uint2*)hi)[i] = *(uint2*)h;
    ((uint2*)lo)[i] = *(uint2*)l;
}

__global__ __launch_bounds__(256) void split_wt(const float* __restrict__ W,
                                                __nv_bfloat16* __restrict__ Th,
                                                __nv_bfloat16* __restrict__ Tl)
{
    __shared__ float tile[32][33];
    const int tx = threadIdx.x, ty = threadIdx.y;        // (32, 8)
    const int bn = blockIdx.x * 32, bk = blockIdx.y * 32;
#pragma unroll
    for (int j = 0; j < 32; j += 8)
        tile[ty + j][tx] = W[(size_t)(bk + ty + j) * DMODEL + bn + tx];
    __syncthreads();
#pragma unroll
    for (int j = 0; j < 32; j += 8) {
        float v = tile[tx][ty + j];
        __nv_bfloat16 h = __float2bfloat16_rn(v);
        __nv_bfloat16 l = __float2bfloat16_rn(v - __bfloat162float(h));
        Th[(size_t)(bn + ty + j) * DMODEL + bk + tx] = h;
        Tl[(size_t)(bn + ty + j) * DMODEL + bk + tx] = l;
    }
}

// ---------------------------------------------------------------------------
// bf16 mma.sync GEMM, 3-term split (unchanged from R4 WIN; 80B-stride rows are
// correct here: BK=32 rows = 64B + 16B pad).
// ---------------------------------------------------------------------------
#define BK        32
#define TILE_B    (128 * 40 * 2)
#define STAGE_B   (4 * TILE_B)
#define NSTAGE    (DMODEL / BK)

extern __shared__ char dyn_smem[];

__global__ __launch_bounds__(256, 2) void gemm_bf16(
    const __nv_bfloat16* __restrict__ Ah, const __nv_bfloat16* __restrict__ Al,
    const __nv_bfloat16* __restrict__ Bh, const __nv_bfloat16* __restrict__ Bl,
    float* __restrict__ Cf, __nv_bfloat16* __restrict__ Ch,
    __nv_bfloat16* __restrict__ Cl, float scale)
{
    const uint32_t sb = smem_u32(dyn_smem);
    const int tid  = threadIdx.x;
    const int lane = tid & 31;
    const int wid  = tid >> 5;
    const int m0   = (wid & 3) * 32;
    const int n0   = (wid >> 2) * 64;
    const int row0 = blockIdx.y * 128;
    const int col0 = blockIdx.x * 128;

    const __nv_bfloat16* srcs[4] = {Ah, Al, Bh, Bl};

    float acc[2][8][4];
#pragma unroll
    for (int a = 0; a < 2; a++)
#pragma unroll
        for (int b = 0; b < 8; b++)
#pragma unroll
            for (int d = 0; d < 4; d++) acc[a][b][d] = 0.f;

    const int a_row = lane & 15;
    const int a_col = 8 * (lane >> 4);
    const int b_row = (lane & 7) + 8 * (lane >> 4);
    const int b_col = 8 * ((lane >> 3) & 1);

    auto load_stage = [&](int s) {
        const uint32_t base = sb + (uint32_t)(s & 1) * STAGE_B;
        const int k0 = s * BK;
#pragma unroll
        for (int t = 0; t < 4; t++) {
            const uint32_t tb = base + (uint32_t)t * TILE_B;
            const int gr0 = (t < 2) ? row0 : col0;
#pragma unroll
            for (int i = 0; i < 2; i++) {
                int f  = tid + i * 256;
                int r  = f >> 2;
                int ch = f & 3;
                cp_async16(tb + (uint32_t)(r * 80 + ch * 16),
                           srcs[t] + (size_t)(gr0 + r) * DMODEL + k0 + ch * 8);
            }
        }
        CP_COMMIT();
    };

    load_stage(0);

    for (int s = 0; s < NSTAGE; s++) {
        if (s + 1 < NSTAGE) { load_stage(s + 1); CP_WAIT(1); }
        else                 { CP_WAIT(0); }
        __syncthreads();

        const uint32_t base = sb + (uint32_t)(s & 1) * STAGE_B;
        const uint32_t aHB = base, aLB = base + TILE_B;
        const uint32_t bHB = base + 2 * TILE_B, bLB = base + 3 * TILE_B;

#pragma unroll
        for (int kk = 0; kk < BK; kk += 16) {
            uint32_t ah[2][4], al[2][4];
#pragma unroll
            for (int mi = 0; mi < 2; mi++) {
                uint32_t off = (uint32_t)((m0 + mi * 16 + a_row) * 80 +
                                          (kk + a_col) * 2);
                ldsm_x4(ah[mi], aHB + off);
                ldsm_x4(al[mi], aLB + off);
            }
#pragma unroll
            for (int ng = 0; ng < 4; ng++) {
                uint32_t boff = (uint32_t)((n0 + ng * 16 + b_row) * 80 +
                                           (kk + b_col) * 2);
                uint32_t bh[4], bl[4];
                ldsm_x4(bh, bHB + boff);
                ldsm_x4(bl, bLB + boff);
#pragma unroll
                for (int mi = 0; mi < 2; mi++) {
                    mma_bf16(acc[mi][2 * ng],     ah[mi], bh[0], bh[1]);
                    mma_bf16(acc[mi][2 * ng + 1], ah[mi], bh[2], bh[3]);
                    mma_bf16(acc[mi][2 * ng],     ah[mi], bl[0], bl[1]);
                    mma_bf16(acc[mi][2 * ng + 1], ah[mi], bl[2], bl[3]);
                    mma_bf16(acc[mi][2 * ng],     al[mi], bh[0], bh[1]);
                    mma_bf16(acc[mi][2 * ng + 1], al[mi], bh[2], bh[3]);
                }
            }
        }
        __syncthreads();
    }

#pragma unroll
    for (int mi = 0; mi < 2; mi++) {
        int r = row0 + m0 + mi * 16 + (lane >> 2);
#pragma unroll
        for (int nj = 0; nj < 8; nj++) {
            int c = col0 + n0 + nj * 8 + (lane & 3) * 2;
            float v0 = acc[mi][nj][0] * scale, v1 = acc[mi][nj][1] * scale;
            float v2 = acc[mi][nj][2] * scale, v3 = acc[mi][nj][3] * scale;
            if (Ch) {
                uint32_t lo0, lo1;
                uint32_t hi0 = split2(v0, v1, lo0);
                uint32_t hi1 = split2(v2, v3, lo1);
                *(uint32_t*)&Ch[(size_t)r * DMODEL + c]       = hi0;
                *(uint32_t*)&Cl[(size_t)r * DMODEL + c]       = lo0;
                *(uint32_t*)&Ch[(size_t)(r + 8) * DMODEL + c] = hi1;
                *(uint32_t*)&Cl[(size_t)(r + 8) * DMODEL + c] = lo1;
            } else {
                *(float2*)&Cf[(size_t)r * DMODEL + c]       = make_float2(v0, v1);
                *(float2*)&Cf[(size_t)(r + 8) * DMODEL + c] = make_float2(v2, v3);
            }
        }
    }
}

// ---------------------------------------------------------------------------
// FlashAttention-2 on mma.sync (bf16 split-precision), causal.
// 128 query rows/CTA (4 warps x m32), Bc=64, double-buffered K/V.
// SMEM: rows are exactly 128B, SW128-swizzled (store & load use same formula).
//   QH @ 0 (16KB), QL @ 16384, then 2 buffers x {KH,KL,VH,VL} of 8KB each.
// ---------------------------------------------------------------------------
#define ATT_QH   0u
#define ATT_QL   16384u
#define ATT_BUF  32768u          // + (t&1)*32768; arrays at +0/8192/16384/24576
#define ATT_SMEM 98304u

__global__ __launch_bounds__(128, 2) void attn_tc()
{
    const uint32_t sb = smem_u32(dyn_smem);
    const int tid  = threadIdx.x;
    const int lane = tid & 31;
    const int wid  = tid >> 5;
    const int m0   = wid * 32;
    const int bh   = blockIdx.y;
    const int base = (bh >> 4) * T_SEQ;
    const int h64  = (bh & 15) * DH;
    const int qb   = ((int)gridDim.x - 1 - (int)blockIdx.x) * 128;  // heavy first
    const int ntiles = qb / 64 + 2;

    // ---- load Q tile (hi/lo), 128 rows x 8 chunks ----
#pragma unroll
    for (int i = 0; i < 8; i++) {
        int f = tid + 128 * i;
        int r = f >> 3, ch = f & 7;
        uint32_t off = SW128((uint32_t)(r * 128 + ch * 16));
        size_t g = (size_t)(base + qb + r) * DMODEL + h64 + ch * 8;
        cp_async16(sb + ATT_QH + off, &g_Qh[g]);
        cp_async16(sb + ATT_QL + off, &g_Ql[g]);
    }
    CP_COMMIT();

    auto load_kv = [&](int t) {
        const uint32_t bufb = sb + ATT_BUF + (uint32_t)(t & 1) * 32768u;
        const int kt = t * 64;
#pragma unroll
        for (int i = 0; i < 4; i++) {
            int f = tid + 128 * i;       // 512 chunks per 64x64 array
            int r = f >> 3, ch = f & 7;
            uint32_t off = SW128((uint32_t)(r * 128 + ch * 16));
            size_t g = (size_t)(base + kt + r) * DMODEL + h64 + ch * 8;
            cp_async16(bufb + off,          &g_Kh[g]);
            cp_async16(bufb + 8192 + off,   &g_Kl[g]);
            cp_async16(bufb + 16384 + off,  &g_Vh[g]);
            cp_async16(bufb + 24576 + off,  &g_Vl[g]);
        }
        CP_COMMIT();
    };

    load_kv(0);

    float o[2][8][4];
#pragma unroll
    for (int a = 0; a < 2; a++)
#pragma unroll
        for (int b = 0; b < 8; b++)
#pragma unroll
            for (int d = 0; d < 4; d++) o[a][b][d] = 0.f;
    float mrow[2][2] = {{-1e30f, -1e30f}, {-1e30f, -1e30f}};
    float lrow[2][2] = {{0.f, 0.f}, {0.f, 0.f}};

    const int a_row = lane & 15;
    const int a_col = 8 * (lane >> 4);                 // bf16 elems
    const int b_row = (lane & 7) + 8 * (lane >> 4);
    const int b_col = 8 * ((lane >> 3) & 1);

    for (int t = 0; t < ntiles; t++) {
        if (t + 1 < ntiles) { load_kv(t + 1); CP_WAIT(1); }
        else                 { CP_WAIT(0); }
        __syncthreads();

        const uint32_t bufb = sb + ATT_BUF + (uint32_t)(t & 1) * 32768u;
        const uint32_t KHb = bufb, KLb = bufb + 8192;
        const uint32_t VHb = bufb + 16384, VLb = bufb + 24576;
        const int kt = t * 64;

        // ---- S = Q K^T (3-term) ----
        float s[2][8][4];
#pragma unroll
        for (int a = 0; a < 2; a++)
#pragma unroll
            for (int b = 0; b < 8; b++)
#pragma unroll
                for (int d = 0; d < 4; d++) s[a][b][d] = 0.f;

#pragma unroll
        for (int ks = 0; ks < 4; ks++) {
            uint32_t qh[2][4], ql[2][4];
#pragma unroll
            for (int mi = 0; mi < 2; mi++) {
                uint32_t off = SW128((uint32_t)((m0 + mi * 16 + a_row) * 128 +
                                                (ks * 16 + a_col) * 2));
                ldsm_x4(qh[mi], sb + ATT_QH + off);
                ldsm_x4(ql[mi], sb + ATT_QL + off);
            }
#pragma unroll
            for (int jp = 0; jp < 4; jp++) {
                uint32_t boff = SW128((uint32_t)((jp * 16 + b_row) * 128 +
                                                 (ks * 16 + b_col) * 2));
                uint32_t kh[4], kl[4];
                ldsm_x4(kh, KHb + boff);
                ldsm_x4(kl, KLb + boff);
#pragma unroll
                for (int mi = 0; mi < 2; mi++) {
                    mma_bf16(s[mi][2 * jp],     qh[mi], kh[0], kh[1]);
                    mma_bf16(s[mi][2 * jp + 1], qh[mi], kh[2], kh[3]);
                    mma_bf16(s[mi][2 * jp],     qh[mi], kl[0], kl[1]);
                    mma_bf16(s[mi][2 * jp + 1], qh[mi], kl[2], kl[3]);
                    mma_bf16(s[mi][2 * jp],     ql[mi], kh[0], kh[1]);
                    mma_bf16(s[mi][2 * jp + 1], ql[mi], kh[2], kh[3]);
                }
            }
        }

        // ---- causal mask (only the two diagonal-crossing tiles) ----
        if (t >= ntiles - 2) {
#pragma unroll
            for (int mi = 0; mi < 2; mi++) {
                int rlo = qb + m0 + mi * 16 + (lane >> 2);
#pragma unroll
                for (int j = 0; j < 8; j++) {
                    int c0 = kt + j * 8 + (lane & 3) * 2;
                    if (c0 > rlo)         s[mi][j][0] = -1e30f;
                    if (c0 + 1 > rlo)     s[mi][j][1] = -1e30f;
                    if (c0 > rlo + 8)     s[mi][j][2] = -1e30f;
                    if (c0 + 1 > rlo + 8) s[mi][j][3] = -1e30f;
                }
            }
        }

        // ---- online softmax (log2 domain; Q pre-scaled) ----
#pragma unroll
        for (int mi = 0; mi < 2; mi++) {
            float mx0 = -1e30f, mx1 = -1e30f;
#pragma unroll
            for (int j = 0; j < 8; j++) {
                mx0 = fmaxf(mx0, fmaxf(s[mi][j][0], s[mi][j][1]));
                mx1 = fmaxf(mx1, fmaxf(s[mi][j][2], s[mi][j][3]));
            }
            mx0 = fmaxf(mx0, __shfl_xor_sync(0xffffffff, mx0, 1));
            mx0 = fmaxf(mx0, __shfl_xor_sync(0xffffffff, mx0, 2));
            mx1 = fmaxf(mx1, __shfl_xor_sync(0xffffffff, mx1, 1));
            mx1 = fmaxf(mx1, __shfl_xor_sync(0xffffffff, mx1, 2));
            float mn0 = fmaxf(mrow[mi][0], mx0), mn1 = fmaxf(mrow[mi][1], mx1);
            float c0 = ex2(mrow[mi][0] - mn0),   c1 = ex2(mrow[mi][1] - mn1);
            mrow[mi][0] = mn0; mrow[mi][1] = mn1;
            lrow[mi][0] *= c0; lrow[mi][1] *= c1;
#pragma unroll
            for (int j = 0; j < 8; j++) {
                o[mi][j][0] *= c0; o[mi][j][1] *= c0;
                o[mi][j][2] *= c1; o[mi][j][3] *= c1;
            }
            float sum0 = 0.f, sum1 = 0.f;
#pragma unroll
            for (int j = 0; j < 8; j++) {
                float p0 = ex2(s[mi][j][0] - mn0);
                float p1 = ex2(s[mi][j][1] - mn0);
                float p2 = ex2(s[mi][j][2] - mn1);
                float p3 = ex2(s[mi][j][3] - mn1);
                s[mi][j][0] = p0; s[mi][j][1] = p1;
                s[mi][j][2] = p2; s[mi][j][3] = p3;
                sum0 += p0 + p1; sum1 += p2 + p3;
            }
            lrow[mi][0] += sum0; lrow[mi][1] += sum1;
        }

        // ---- O += P V (3-term; P from S frags via C->A identity) ----
#pragma unroll
        for (int ks = 0; ks < 4; ks++) {
            uint32_t ph[2][4], pl[2][4];
#pragma unroll
            for (int mi = 0; mi < 2; mi++) {
                ph[mi][0] = split2(s[mi][2 * ks][0],     s[mi][2 * ks][1],     pl[mi][0]);
                ph[mi][1] = split2(s[mi][2 * ks][2],     s[mi][2 * ks][3],     pl[mi][1]);
                ph[mi][2] = split2(s[mi][2 * ks + 1][0], s[mi][2 * ks + 1][1], pl[mi][2]);
                ph[mi][3] = split2(s[mi][2 * ks + 1][2], s[mi][2 * ks + 1][3], pl[mi][3]);
            }
#pragma unroll
            for (int jp = 0; jp < 4; jp++) {
                uint32_t voff = SW128((uint32_t)((ks * 16 + a_row) * 128 +
                                                 (jp * 16 + a_col) * 2));
                uint32_t vh[4], vl[4];
                ldsm_x4_t(vh, VHb + voff);
                ldsm_x4_t(vl, VLb + voff);
#pragma unroll
                for (int mi = 0; mi < 2; mi++) {
                    mma_bf16(o[mi][2 * jp],     ph[mi], vh[0], vh[1]);
                    mma_bf16(o[mi][2 * jp + 1], ph[mi], vh[2], vh[3]);
                    mma_bf16(o[mi][2 * jp],     ph[mi], vl[0], vl[1]);
                    mma_bf16(o[mi][2 * jp + 1], ph[mi], vl[2], vl[3]);
                    mma_bf16(o[mi][2 * jp],     pl[mi], vh[0], vh[1]);
                    mma_bf16(o[mi][2 * jp + 1], pl[mi], vh[2], vh[3]);
                }
            }
        }
        __syncthreads();
    }

    // ---- finalize: z = O/l, write Zh/Zl ----
#pragma unroll
    for (int mi = 0; mi < 2; mi++) {
        float l0 = lrow[mi][0], l1 = lrow[mi][1];
        l0 += __shfl_xor_sync(0xffffffff, l0, 1);
        l0 += __shfl_xor_sync(0xffffffff, l0, 2);
        l1 += __shfl_xor_sync(0xffffffff, l1, 1);
        l1 += __shfl_xor_sync(0xffffffff, l1, 2);
        float inv0 = 1.f / l0, inv1 = 1.f / l1;
        size_t rlo = (size_t)(base + qb + m0 + mi * 16 + (lane >> 2)) * DMODEL;
        size_t rhi = rlo + 8 * DMODEL;
#pragma unroll
        for (int j = 0; j < 8; j++) {
            int c = h64 + j * 8 + (lane & 3) * 2;
            uint32_t lo0, lo1;
            uint32_t hi0 = split2(o[mi][j][0] * inv0, o[mi][j][1] * inv0, lo0);
            uint32_t hi1 = split2(o[mi][j][2] * inv1, o[mi][j][3] * inv1, lo1);
            *(uint32_t*)&g_Zh[rlo + c] = hi0;
            *(uint32_t*)&g_Zl[rlo + c] = lo0;
            *(uint32_t*)&g_Zh[rhi + c] = hi1;
            *(uint32_t*)&g_Zl[rhi + c] = lo1;
        }
    }
}

// ---------------------------------------------------------------------------
extern "C" void kernel_launch(void* const* d_in, const int* in_sizes, int n_in,
                              void* d_out, int out_size)
{
    const float* x  = (const float*)d_in[0];
    const float* Wq = (const float*)d_in[1];
    const float* Wk = (const float*)d_in[2];
    const float* Wv = (const float*)d_in[3];
    const float* Wo = (const float*)d_in[4];
    float* out = (float*)d_out;

    __nv_bfloat16 *xh, *xl, *Qh, *Ql, *Kh, *Kl, *Vh, *Vl, *Zh, *Zl;
    __nv_bfloat16 *Wqh, *Wql, *Wkh, *Wkl, *Wvh, *Wvl, *Woh, *Wol;
    cudaGetSymbolAddress((void**)&xh, g_xh);   cudaGetSymbolAddress((void**)&xl, g_xl);
    cudaGetSymbolAddress((void**)&Qh, g_Qh);   cudaGetSymbolAddress((void**)&Ql, g_Ql);
    cudaGetSymbolAddress((void**)&Kh, g_Kh);   cudaGetSymbolAddress((void**)&Kl, g_Kl);
    cudaGetSymbolAddress((void**)&Vh, g_Vh);   cudaGetSymbolAddress((void**)&Vl, g_Vl);
    cudaGetSymbolAddress((void**)&Zh, g_Zh);   cudaGetSymbolAddress((void**)&Zl, g_Zl);
    cudaGetSymbolAddress((void**)&Wqh, g_Wqh); cudaGetSymbolAddress((void**)&Wql, g_Wql);
    cudaGetSymbolAddress((void**)&Wkh, g_Wkh); cudaGetSymbolAddress((void**)&Wkl, g_Wkl);
    cudaGetSymbolAddress((void**)&Wvh, g_Wvh); cudaGetSymbolAddress((void**)&Wvl, g_Wvl);
    cudaGetSymbolAddress((void**)&Woh, g_Woh); cudaGetSymbolAddress((void**)&Wol, g_Wol);

    cudaFuncSetAttribute(gemm_bf16, cudaFuncAttributeMaxDynamicSharedMemorySize,
                         2 * STAGE_B);
    cudaFuncSetAttribute(attn_tc, cudaFuncAttributeMaxDynamicSharedMemorySize,
                         ATT_SMEM);

    const int nx4 = MROWS * DMODEL / 4;
    dim3 tblk(32, 8), tgrd(DMODEL / 32, DMODEL / 32);

    split_x<<<(nx4 + 255) / 256, 256>>>(x, xh, xl, nx4);
    split_wt<<<tgrd, tblk>>>(Wq, Wqh, Wql);
    split_wt<<<tgrd, tblk>>>(Wk, Wkh, Wkl);
    split_wt<<<tgrd, tblk>>>(Wv, Wvh, Wvl);
    split_wt<<<tgrd, tblk>>>(Wo, Woh, Wol);

    dim3 ggrid(DMODEL / 128, MROWS / 128);   // (8, 32)
    gemm_bf16<<<ggrid, 256, 2 * STAGE_B>>>(xh, xl, Wqh, Wql, nullptr, Qh, Ql, QSCALE);
    gemm_bf16<<<ggrid, 256, 2 * STAGE_B>>>(xh, xl, Wkh, Wkl, nullptr, Kh, Kl, 1.0f);
    gemm_bf16<<<ggrid, 256, 2 * STAGE_B>>>(xh, xl, Wvh, Wvl, nullptr, Vh, Vl, 1.0f);

    attn_tc<<<dim3(T_SEQ / 128, NB * NH), 128, ATT_SMEM>>>();

    gemm_bf16<<<ggrid, 256, 2 * STAGE_B>>>(Zh, Zl, Woh, Wol, out, nullptr, nullptr, 1.0f);
}

// round 9
// speedup vs baseline: 4.1343x; 1.4602x over previous
#include <cuda_runtime.h>
#include <cuda_bf16.h>
#include <cstdint>

#define MROWS  4096   // B*T
#define DMODEL 1024
#define T_SEQ  2048
#define NB     2
#define NH     16
#define DH     64
#define QSCALE 0.1803368801111244f   // 0.125 * log2(e)

// ---------------- scratch (__device__ globals: allocation-free rule) --------
__device__ __nv_bfloat16 g_xh[MROWS * DMODEL],  g_xl[MROWS * DMODEL];
__device__ __nv_bfloat16 g_Qh[MROWS * DMODEL],  g_Ql[MROWS * DMODEL];
__device__ __nv_bfloat16 g_Kh[MROWS * DMODEL],  g_Kl[MROWS * DMODEL];
__device__ __nv_bfloat16 g_Vh[MROWS * DMODEL],  g_Vl[MROWS * DMODEL];
__device__ __nv_bfloat16 g_Zh[MROWS * DMODEL],  g_Zl[MROWS * DMODEL];
__device__ __nv_bfloat16 g_Wqh[DMODEL * DMODEL], g_Wql[DMODEL * DMODEL];
__device__ __nv_bfloat16 g_Wkh[DMODEL * DMODEL], g_Wkl[DMODEL * DMODEL];
__device__ __nv_bfloat16 g_Wvh[DMODEL * DMODEL], g_Wvl[DMODEL * DMODEL];
__device__ __nv_bfloat16 g_Woh[DMODEL * DMODEL], g_Wol[DMODEL * DMODEL];

// ---------------------------------------------------------------------------
// PTX helpers (plain sm_103: cp.async, ldmatrix, mma.sync, ex2.approx)
// ---------------------------------------------------------------------------
__device__ __forceinline__ uint32_t smem_u32(const void* p) {
    uint32_t a;
    asm("{ .reg .u64 t; cvta.to.shared.u64 t, %1; cvt.u32.u64 %0, t; }"
        : "=r"(a) : "l"(p));
    return a;
}

__device__ __forceinline__ void cp_async16(uint32_t dst, const void* src) {
    asm volatile("cp.async.cg.shared.global [%0], [%1], 16;"
                 :: "r"(dst), "l"(src));
}
#define CP_COMMIT() asm volatile("cp.async.commit_group;" ::: "memory")
#define CP_WAIT(n)  asm volatile("cp.async.wait_group %0;" :: "n"(n) : "memory")

// 128B-row XOR swizzle (chunk ^= row&7) — same formula at store and load
#define SW128(off) ((off) ^ (((off) >> 3) & 0x70))

__device__ __forceinline__ void ldsm_x4(uint32_t* r, uint32_t addr) {
    asm volatile("ldmatrix.sync.aligned.m8n8.x4.shared.b16 {%0,%1,%2,%3}, [%4];"
                 : "=r"(r[0]), "=r"(r[1]), "=r"(r[2]), "=r"(r[3]) : "r"(addr));
}
__device__ __forceinline__ void ldsm_x4_t(uint32_t* r, uint32_t addr) {
    asm volatile("ldmatrix.sync.aligned.m8n8.x4.trans.shared.b16 {%0,%1,%2,%3}, [%4];"
                 : "=r"(r[0]), "=r"(r[1]), "=r"(r[2]), "=r"(r[3]) : "r"(addr));
}

__device__ __forceinline__ void mma_bf16(float* c, const uint32_t* a,
                                         uint32_t b0, uint32_t b1) {
    asm volatile(
        "mma.sync.aligned.m16n8k16.row.col.f32.bf16.bf16.f32 "
        "{%0,%1,%2,%3}, {%4,%5,%6,%7}, {%8,%9}, {%0,%1,%2,%3};"
        : "+f"(c[0]), "+f"(c[1]), "+f"(c[2]), "+f"(c[3])
        : "r"(a[0]), "r"(a[1]), "r"(a[2]), "r"(a[3]), "r"(b0), "r"(b1));
}

__device__ __forceinline__ float ex2(float x) {
    float r;
    asm("ex2.approx.f32 %0, %1;" : "=f"(r) : "f"(x));
    return r;
}

__device__ __forceinline__ uint32_t split2(float v0, float v1, uint32_t& lo) {
    __nv_bfloat16 h0 = __float2bfloat16_rn(v0), h1 = __float2bfloat16_rn(v1);
    float l0 = v0 - __bfloat162float(h0), l1 = v1 - __bfloat162float(h1);
    __nv_bfloat16 L0 = __float2bfloat16_rn(l0), L1 = __float2bfloat16_rn(l1);
    lo = (uint32_t)__bfloat16_as_ushort(L0) | ((uint32_t)__bfloat16_as_ushort(L1) << 16);
    return (uint32_t)__bfloat16_as_ushort(h0) | ((uint32_t)__bfloat16_as_ushort(h1) << 16);
}

// ---------------------------------------------------------------------------
// Split kernels (inputs only)
// ---------------------------------------------------------------------------
__global__ __launch_bounds__(256) void split_x(const float* __restrict__ src,
                                               __nv_bfloat16* __restrict__ hi,
                                               __nv_bfloat16* __restrict__ lo, int n4)
{
    int i = blockIdx.x * 256 + threadIdx.x;
    if (i >= n4) return;
    float4 v = ((const float4*)src)[i];
    __nv_bfloat16 h[4], l[4];
    float vv[4] = {v.x, v.y, v.z, v.w};
#pragma unroll
    for (int k = 0; k < 4; k++) {
        h[k] = __float2bfloat16_rn(vv[k]);
        l[k] = __float2bfloat16_rn(vv[k] - __bfloat162float(h[k]));
    }
    ((uint2*)hi)[i] = *(uint2*)h;
    ((uint2*)lo)[i] = *(uint2*)l;
}

__global__ __launch_bounds__(256) void split_wt(const float* __restrict__ W,
                                                __nv_bfloat16* __restrict__ Th,
                                                __nv_bfloat16* __restrict__ Tl)
{
    __shared__ float tile[32][33];
    const int tx = threadIdx.x, ty = threadIdx.y;        // (32, 8)
    const int bn = blockIdx.x * 32, bk = blockIdx.y * 32;
#pragma unroll
    for (int j = 0; j < 32; j += 8)
        tile[ty + j][tx] = W[(size_t)(bk + ty + j) * DMODEL + bn + tx];
    __syncthreads();
#pragma unroll
    for (int j = 0; j < 32; j += 8) {
        float v = tile[tx][ty + j];
        __nv_bfloat16 h = __float2bfloat16_rn(v);
        __nv_bfloat16 l = __float2bfloat16_rn(v - __bfloat162float(h));
        Th[(size_t)(bn + ty + j) * DMODEL + bk + tx] = h;
        Tl[(size_t)(bn + ty + j) * DMODEL + bk + tx] = l;
    }
}

// ---------------------------------------------------------------------------
// bf16 mma.sync GEMM, 3-term split (unchanged — at HMMA issue floor).
// ---------------------------------------------------------------------------
#define BK        32
#define TILE_B    (128 * 40 * 2)
#define STAGE_B   (4 * TILE_B)
#define NSTAGE    (DMODEL / BK)

extern __shared__ char dyn_smem[];

__global__ __launch_bounds__(256, 2) void gemm_bf16(
    const __nv_bfloat16* __restrict__ Ah, const __nv_bfloat16* __restrict__ Al,
    const __nv_bfloat16* __restrict__ Bh, const __nv_bfloat16* __restrict__ Bl,
    float* __restrict__ Cf, __nv_bfloat16* __restrict__ Ch,
    __nv_bfloat16* __restrict__ Cl, float scale)
{
    const uint32_t sb = smem_u32(dyn_smem);
    const int tid  = threadIdx.x;
    const int lane = tid & 31;
    const int wid  = tid >> 5;
    const int m0   = (wid & 3) * 32;
    const int n0   = (wid >> 2) * 64;
    const int row0 = blockIdx.y * 128;
    const int col0 = blockIdx.x * 128;

    const __nv_bfloat16* srcs[4] = {Ah, Al, Bh, Bl};

    float acc[2][8][4];
#pragma unroll
    for (int a = 0; a < 2; a++)
#pragma unroll
        for (int b = 0; b < 8; b++)
#pragma unroll
            for (int d = 0; d < 4; d++) acc[a][b][d] = 0.f;

    const int a_row = lane & 15;
    const int a_col = 8 * (lane >> 4);
    const int b_row = (lane & 7) + 8 * (lane >> 4);
    const int b_col = 8 * ((lane >> 3) & 1);

    auto load_stage = [&](int s) {
        const uint32_t base = sb + (uint32_t)(s & 1) * STAGE_B;
        const int k0 = s * BK;
#pragma unroll
        for (int t = 0; t < 4; t++) {
            const uint32_t tb = base + (uint32_t)t * TILE_B;
            const int gr0 = (t < 2) ? row0 : col0;
#pragma unroll
            for (int i = 0; i < 2; i++) {
                int f  = tid + i * 256;
                int r  = f >> 2;
                int ch = f & 3;
                cp_async16(tb + (uint32_t)(r * 80 + ch * 16),
                           srcs[t] + (size_t)(gr0 + r) * DMODEL + k0 + ch * 8);
            }
        }
        CP_COMMIT();
    };

    load_stage(0);

    for (int s = 0; s < NSTAGE; s++) {
        if (s + 1 < NSTAGE) { load_stage(s + 1); CP_WAIT(1); }
        else                 { CP_WAIT(0); }
        __syncthreads();

        const uint32_t base = sb + (uint32_t)(s & 1) * STAGE_B;
        const uint32_t aHB = base, aLB = base + TILE_B;
        const uint32_t bHB = base + 2 * TILE_B, bLB = base + 3 * TILE_B;

#pragma unroll
        for (int kk = 0; kk < BK; kk += 16) {
            uint32_t ah[2][4], al[2][4];
#pragma unroll
            for (int mi = 0; mi < 2; mi++) {
                uint32_t off = (uint32_t)((m0 + mi * 16 + a_row) * 80 +
                                          (kk + a_col) * 2);
                ldsm_x4(ah[mi], aHB + off);
                ldsm_x4(al[mi], aLB + off);
            }
#pragma unroll
            for (int ng = 0; ng < 4; ng++) {
                uint32_t boff = (uint32_t)((n0 + ng * 16 + b_row) * 80 +
                                           (kk + b_col) * 2);
                uint32_t bh[4], bl[4];
                ldsm_x4(bh, bHB + boff);
                ldsm_x4(bl, bLB + boff);
#pragma unroll
                for (int mi = 0; mi < 2; mi++) {
                    mma_bf16(acc[mi][2 * ng],     ah[mi], bh[0], bh[1]);
                    mma_bf16(acc[mi][2 * ng + 1], ah[mi], bh[2], bh[3]);
                    mma_bf16(acc[mi][2 * ng],     ah[mi], bl[0], bl[1]);
                    mma_bf16(acc[mi][2 * ng + 1], ah[mi], bl[2], bl[3]);
                    mma_bf16(acc[mi][2 * ng],     al[mi], bh[0], bh[1]);
                    mma_bf16(acc[mi][2 * ng + 1], al[mi], bh[2], bh[3]);
                }
            }
        }
        __syncthreads();
    }

#pragma unroll
    for (int mi = 0; mi < 2; mi++) {
        int r = row0 + m0 + mi * 16 + (lane >> 2);
#pragma unroll
        for (int nj = 0; nj < 8; nj++) {
            int c = col0 + n0 + nj * 8 + (lane & 3) * 2;
            float v0 = acc[mi][nj][0] * scale, v1 = acc[mi][nj][1] * scale;
            float v2 = acc[mi][nj][2] * scale, v3 = acc[mi][nj][3] * scale;
            if (Ch) {
                uint32_t lo0, lo1;
                uint32_t hi0 = split2(v0, v1, lo0);
                uint32_t hi1 = split2(v2, v3, lo1);
                *(uint32_t*)&Ch[(size_t)r * DMODEL + c]       = hi0;
                *(uint32_t*)&Cl[(size_t)r * DMODEL + c]       = lo0;
                *(uint32_t*)&Ch[(size_t)(r + 8) * DMODEL + c] = hi1;
                *(uint32_t*)&Cl[(size_t)(r + 8) * DMODEL + c] = lo1;
            } else {
                *(float2*)&Cf[(size_t)r * DMODEL + c]       = make_float2(v0, v1);
                *(float2*)&Cf[(size_t)(r + 8) * DMODEL + c] = make_float2(v2, v3);
            }
        }
    }
}

// ---------------------------------------------------------------------------
// FlashAttention-2 on mma.sync, causal, bf16 split-precision.
// 256 threads = 8 warps, warp tile m16 (16 query rows), Bc=64, double-buffered
// K/V, Q fragments held in registers across the whole KV loop.
// SMEM layout identical to R7 (96KB): QH@0, QL@16K, 2 x {KH,KL,VH,VL} 8K each.
// ---------------------------------------------------------------------------
#define ATT_QH   0u
#define ATT_QL   16384u
#define ATT_BUF  32768u
#define ATT_SMEM 98304u

__global__ __launch_bounds__(256, 2) void attn_tc()
{
    const uint32_t sb = smem_u32(dyn_smem);
    const int tid  = threadIdx.x;
    const int lane = tid & 31;
    const int wid  = tid >> 5;
    const int m0   = wid * 16;
    const int bh   = blockIdx.y;
    const int base = (bh >> 4) * T_SEQ;
    const int h64  = (bh & 15) * DH;
    const int qb   = ((int)gridDim.x - 1 - (int)blockIdx.x) * 128;  // heavy first
    const int ntiles = qb / 64 + 2;

    // ---- load Q tile (hi/lo): 1024 chunks per array, 256 threads x 4 ----
#pragma unroll
    for (int i = 0; i < 4; i++) {
        int f = tid + 256 * i;
        int r = f >> 3, ch = f & 7;
        uint32_t off = SW128((uint32_t)(r * 128 + ch * 16));
        size_t g = (size_t)(base + qb + r) * DMODEL + h64 + ch * 8;
        cp_async16(sb + ATT_QH + off, &g_Qh[g]);
        cp_async16(sb + ATT_QL + off, &g_Ql[g]);
    }
    CP_COMMIT();

    auto load_kv = [&](int t) {
        const uint32_t bufb = sb + ATT_BUF + (uint32_t)(t & 1) * 32768u;
        const int kt = t * 64;
#pragma unroll
        for (int i = 0; i < 2; i++) {
            int f = tid + 256 * i;       // 512 chunks per 64x64 array
            int r = f >> 3, ch = f & 7;
            uint32_t off = SW128((uint32_t)(r * 128 + ch * 16));
            size_t g = (size_t)(base + kt + r) * DMODEL + h64 + ch * 8;
            cp_async16(bufb + off,          &g_Kh[g]);
            cp_async16(bufb + 8192 + off,   &g_Kl[g]);
            cp_async16(bufb + 16384 + off,  &g_Vh[g]);
            cp_async16(bufb + 24576 + off,  &g_Vl[g]);
        }
        CP_COMMIT();
    };

    load_kv(0);

    const int a_row = lane & 15;
    const int a_col = 8 * (lane >> 4);
    const int b_row = (lane & 7) + 8 * (lane >> 4);
    const int b_col = 8 * ((lane >> 3) & 1);

    // ---- hoist Q fragments into registers (Q smem read exactly once) ----
    CP_WAIT(1);                      // Q group (oldest) complete
    __syncthreads();
    uint32_t qh[4][4], ql[4][4];
#pragma unroll
    for (int ks = 0; ks < 4; ks++) {
        uint32_t off = SW128((uint32_t)((m0 + a_row) * 128 + (ks * 16 + a_col) * 2));
        ldsm_x4(qh[ks], sb + ATT_QH + off);
        ldsm_x4(ql[ks], sb + ATT_QL + off);
    }

    float o[8][4];
#pragma unroll
    for (int b = 0; b < 8; b++)
#pragma unroll
        for (int d = 0; d < 4; d++) o[b][d] = 0.f;
    float mrow[2] = {-1e30f, -1e30f};
    float lrow[2] = {0.f, 0.f};

    for (int t = 0; t < ntiles; t++) {
        if (t + 1 < ntiles) { load_kv(t + 1); CP_WAIT(1); }
        else                 { CP_WAIT(0); }
        __syncthreads();

        const uint32_t bufb = sb + ATT_BUF + (uint32_t)(t & 1) * 32768u;
        const uint32_t KHb = bufb, KLb = bufb + 8192;
        const uint32_t VHb = bufb + 16384, VLb = bufb + 24576;
        const int kt = t * 64;

        // ---- S = Q K^T (3-term) ----
        float s[8][4];
#pragma unroll
        for (int b = 0; b < 8; b++)
#pragma unroll
            for (int d = 0; d < 4; d++) s[b][d] = 0.f;

#pragma unroll
        for (int ks = 0; ks < 4; ks++) {
#pragma unroll
            for (int jp = 0; jp < 4; jp++) {
                uint32_t boff = SW128((uint32_t)((jp * 16 + b_row) * 128 +
                                                 (ks * 16 + b_col) * 2));
                uint32_t kh[4], kl[4];
                ldsm_x4(kh, KHb + boff);
                ldsm_x4(kl, KLb + boff);
                mma_bf16(s[2 * jp],     qh[ks], kh[0], kh[1]);
                mma_bf16(s[2 * jp + 1], qh[ks], kh[2], kh[3]);
                mma_bf16(s[2 * jp],     qh[ks], kl[0], kl[1]);
                mma_bf16(s[2 * jp + 1], qh[ks], kl[2], kl[3]);
                mma_bf16(s[2 * jp],     ql[ks], kh[0], kh[1]);
                mma_bf16(s[2 * jp + 1], ql[ks], kh[2], kh[3]);
            }
        }

        // ---- causal mask (only the two diagonal-crossing tiles) ----
        if (t >= ntiles - 2) {
            int rlo = qb + m0 + (lane >> 2);
#pragma unroll
            for (int j = 0; j < 8; j++) {
                int c0 = kt + j * 8 + (lane & 3) * 2;
                if (c0 > rlo)         s[j][0] = -1e30f;
                if (c0 + 1 > rlo)     s[j][1] = -1e30f;
                if (c0 > rlo + 8)     s[j][2] = -1e30f;
                if (c0 + 1 > rlo + 8) s[j][3] = -1e30f;
            }
        }

        // ---- online softmax (log2 domain; Q pre-scaled) ----
        {
            float mx0 = -1e30f, mx1 = -1e30f;
#pragma unroll
            for (int j = 0; j < 8; j++) {
                mx0 = fmaxf(mx0, fmaxf(s[j][0], s[j][1]));
                mx1 = fmaxf(mx1, fmaxf(s[j][2], s[j][3]));
            }
            mx0 = fmaxf(mx0, __shfl_xor_sync(0xffffffff, mx0, 1));
            mx0 = fmaxf(mx0, __shfl_xor_sync(0xffffffff, mx0, 2));
            mx1 = fmaxf(mx1, __shfl_xor_sync(0xffffffff, mx1, 1));
            mx1 = fmaxf(mx1, __shfl_xor_sync(0xffffffff, mx1, 2));
            float mn0 = fmaxf(mrow[0], mx0), mn1 = fmaxf(mrow[1], mx1);
            float c0 = ex2(mrow[0] - mn0),   c1 = ex2(mrow[1] - mn1);
            mrow[0] = mn0; mrow[1] = mn1;
            lrow[0] *= c0; lrow[1] *= c1;
#pragma unroll
            for (int j = 0; j < 8; j++) {
                o[j][0] *= c0; o[j][1] *= c0;
                o[j][2] *= c1; o[j][3] *= c1;
            }
            float sum0 = 0.f, sum1 = 0.f;
#pragma unroll
            for (int j = 0; j < 8; j++) {
                float p0 = ex2(s[j][0] - mn0);
                float p1 = ex2(s[j][1] - mn0);
                float p2 = ex2(s[j][2] - mn1);
                float p3 = ex2(s[j][3] - mn1);
                s[j][0] = p0; s[j][1] = p1;
                s[j][2] = p2; s[j][3] = p3;
                sum0 += p0 + p1; sum1 += p2 + p3;
            }
            lrow[0] += sum0; lrow[1] += sum1;
        }

        // ---- O += P V (3-term; P from S frags via C->A identity) ----
#pragma unroll
        for (int ks = 0; ks < 4; ks++) {
            uint32_t ph[4], pl[4];
            ph[0] = split2(s[2 * ks][0],     s[2 * ks][1],     pl[0]);
            ph[1] = split2(s[2 * ks][2],     s[2 * ks][3],     pl[1]);
            ph[2] = split2(s[2 * ks + 1][0], s[2 * ks + 1][1], pl[2]);
            ph[3] = split2(s[2 * ks + 1][2], s[2 * ks + 1][3], pl[3]);
#pragma unroll
            for (int jp = 0; jp < 4; jp++) {
                uint32_t voff = SW128((uint32_t)((ks * 16 + a_row) * 128 +
                                                 (jp * 16 + a_col) * 2));
                uint32_t vh[4], vl[4];
                ldsm_x4_t(vh, VHb + voff);
                ldsm_x4_t(vl, VLb + voff);
                mma_bf16(o[2 * jp],     ph, vh[0], vh[1]);
                mma_bf16(o[2 * jp + 1], ph, vh[2], vh[3]);
                mma_bf16(o[2 * jp],     ph, vl[0], vl[1]);
                mma_bf16(o[2 * jp + 1], ph, vl[2], vl[3]);
                mma_bf16(o[2 * jp],     pl, vh[0], vh[1]);
                mma_bf16(o[2 * jp + 1], pl, vh[2], vh[3]);
            }
        }
        __syncthreads();
    }

    // ---- finalize: z = O/l, write Zh/Zl ----
    {
        float l0 = lrow[0], l1 = lrow[1];
        l0 += __shfl_xor_sync(0xffffffff, l0, 1);
        l0 += __shfl_xor_sync(0xffffffff, l0, 2);
        l1 += __shfl_xor_sync(0xffffffff, l1, 1);
        l1 += __shfl_xor_sync(0xffffffff, l1, 2);
        float inv0 = 1.f / l0, inv1 = 1.f / l1;
        size_t rlo = (size_t)(base + qb + m0 + (lane >> 2)) * DMODEL;
        size_t rhi = rlo + 8 * DMODEL;
#pragma unroll
        for (int j = 0; j < 8; j++) {
            int c = h64 + j * 8 + (lane & 3) * 2;
            uint32_t lo0, lo1;
            uint32_t hi0 = split2(o[j][0] * inv0, o[j][1] * inv0, lo0);
            uint32_t hi1 = split2(o[j][2] * inv1, o[j][3] * inv1, lo1);
            *(uint32_t*)&g_Zh[rlo + c] = hi0;
            *(uint32_t*)&g_Zl[rlo + c] = lo0;
            *(uint32_t*)&g_Zh[rhi + c] = hi1;
            *(uint32_t*)&g_Zl[rhi + c] = lo1;
        }
    }
}

// ---------------------------------------------------------------------------
extern "C" void kernel_launch(void* const* d_in, const int* in_sizes, int n_in,
                              void* d_out, int out_size)
{
    const float* x  = (const float*)d_in[0];
    const float* Wq = (const float*)d_in[1];
    const float* Wk = (const float*)d_in[2];
    const float* Wv = (const float*)d_in[3];
    const float* Wo = (const float*)d_in[4];
    float* out = (float*)d_out;

    __nv_bfloat16 *xh, *xl, *Qh, *Ql, *Kh, *Kl, *Vh, *Vl, *Zh, *Zl;
    __nv_bfloat16 *Wqh, *Wql, *Wkh, *Wkl, *Wvh, *Wvl, *Woh, *Wol;
    cudaGetSymbolAddress((void**)&xh, g_xh);   cudaGetSymbolAddress((void**)&xl, g_xl);
    cudaGetSymbolAddress((void**)&Qh, g_Qh);   cudaGetSymbolAddress((void**)&Ql, g_Ql);
    cudaGetSymbolAddress((void**)&Kh, g_Kh);   cudaGetSymbolAddress((void**)&Kl, g_Kl);
    cudaGetSymbolAddress((void**)&Vh, g_Vh);   cudaGetSymbolAddress((void**)&Vl, g_Vl);
    cudaGetSymbolAddress((void**)&Zh, g_Zh);   cudaGetSymbolAddress((void**)&Zl, g_Zl);
    cudaGetSymbolAddress((void**)&Wqh, g_Wqh); cudaGetSymbolAddress((void**)&Wql, g_Wql);
    cudaGetSymbolAddress((void**)&Wkh, g_Wkh); cudaGetSymbolAddress((void**)&Wkl, g_Wkl);
    cudaGetSymbolAddress((void**)&Wvh, g_Wvh); cudaGetSymbolAddress((void**)&Wvl, g_Wvl);
    cudaGetSymbolAddress((void**)&Woh, g_Woh); cudaGetSymbolAddress((void**)&Wol, g_Wol);

    cudaFuncSetAttribute(gemm_bf16, cudaFuncAttributeMaxDynamicSharedMemorySize,
                         2 * STAGE_B);
    cudaFuncSetAttribute(attn_tc, cudaFuncAttributeMaxDynamicSharedMemorySize,
                         ATT_SMEM);

    const int nx4 = MROWS * DMODEL / 4;
    dim3 tblk(32, 8), tgrd(DMODEL / 32, DMODEL / 32);

    split_x<<<(nx4 + 255) / 256, 256>>>(x, xh, xl, nx4);
    split_wt<<<tgrd, tblk>>>(Wq, Wqh, Wql);
    split_wt<<<tgrd, tblk>>>(Wk, Wkh, Wkl);
    split_wt<<<tgrd, tblk>>>(Wv, Wvh, Wvl);
    split_wt<<<tgrd, tblk>>>(Wo, Woh, Wol);

    dim3 ggrid(DMODEL / 128, MROWS / 128);   // (8, 32)
    gemm_bf16<<<ggrid, 256, 2 * STAGE_B>>>(xh, xl, Wqh, Wql, nullptr, Qh, Ql, QSCALE);
    gemm_bf16<<<ggrid, 256, 2 * STAGE_B>>>(xh, xl, Wkh, Wkl, nullptr, Kh, Kl, 1.0f);
    gemm_bf16<<<ggrid, 256, 2 * STAGE_B>>>(xh, xl, Wvh, Wvl, nullptr, Vh, Vl, 1.0f);

    attn_tc<<<dim3(T_SEQ / 128, NB * NH), 256, ATT_SMEM>>>();

    gemm_bf16<<<ggrid, 256, 2 * STAGE_B>>>(Zh, Zl, Woh, Wol, out, nullptr, nullptr, 1.0f);
}